// round 9
// baseline (speedup 1.0000x reference)
#include <cuda_runtime.h>
#include <cstdint>

#define GG    49
#define CQ    64
#define NEGV  (-1e20f)

// Softmax probabilities scratch: [n][49][16]; pH at slots 0..6 (7=0), pW at 8..14 (15=0).
__device__ float g_p[512 * GG * 16];

__device__ __forceinline__ uint32_t smem_u32(const void* p) {
    uint32_t a;
    asm("{ .reg .u64 t; cvta.to.shared.u64 t, %1; cvt.u32.u64 %0, t; }"
        : "=r"(a) : "l"(p));
    return a;
}
#define CP_ASYNC16(dst, src) \
    asm volatile("cp.async.ca.shared.global [%0], [%1], 16;" :: "r"(dst), "l"(src))
#define CP_COMMIT() asm volatile("cp.async.commit_group;" ::: "memory")
#define CP_WAIT0()  asm volatile("cp.async.wait_group 0;" ::: "memory")

// ---------------------------------------------------------------------------
// Kernel A: logits (H diag-masked + W) + softmax over 14, per n.  (unchanged)
// grid = N, block = 384, dyn smem 56448 B -> 4 blocks/SM.
// ---------------------------------------------------------------------------
__global__ __launch_bounds__(384) void ax_attn_logits(
    const float* __restrict__ qH, const float* __restrict__ kH,
    const float* __restrict__ qW, const float* __restrict__ kW)
{
    extern __shared__ float smA[];
    float* sQH = smA;              // 49 * 68
    float* sKH = smA + 3332;       // transposed [w*7+j][c], 49 * 68
    float* sQW = smA + 6664;
    float* sKW = smA + 9996;
    float* sL  = smA + 13328;      // 49 * 16

    const int n   = blockIdx.x;
    const int tid = threadIdx.x;

    const float4* q1 = (const float4*)(qH + (size_t)n * 3136);
    const float4* q2 = (const float4*)(qW + (size_t)n * 3136);
    const float4* k1 = (const float4*)(kH + (size_t)n * 3136);
    const float4* k2 = (const float4*)(kW + (size_t)n * 3136);

    {
        float4 a0q, a1q, b0q, b1q, a0k, a1k, b0k, b1k;
        int ia = tid, ib = tid + 384;
        a0q = q1[ia]; b0q = q2[ia]; a0k = k1[ia]; b0k = k2[ia];
        if (ib < 784) { a1q = q1[ib]; b1q = q2[ib]; a1k = k1[ib]; b1k = k2[ib]; }

        {
            int g = ia >> 4, c4 = ia & 15;
            ((float4*)(sQH + g * 68))[c4] = a0q;
            ((float4*)(sQW + g * 68))[c4] = b0q;
            int w = ia / 112, r4 = ia - w * 112, r = 4 * r4;
            int c = r / 7, j = r - 7 * c;
            float av[4] = {a0k.x, a0k.y, a0k.z, a0k.w};
            float bv[4] = {b0k.x, b0k.y, b0k.z, b0k.w};
            #pragma unroll
            for (int e = 0; e < 4; e++) {
                sKH[(w * 7 + j) * 68 + c] = av[e];
                sKW[(w * 7 + j) * 68 + c] = bv[e];
                if (++j == 7) { j = 0; c++; }
            }
        }
        if (ib < 784) {
            int g = ib >> 4, c4 = ib & 15;
            ((float4*)(sQH + g * 68))[c4] = a1q;
            ((float4*)(sQW + g * 68))[c4] = b1q;
            int w = ib / 112, r4 = ib - w * 112, r = 4 * r4;
            int c = r / 7, j = r - 7 * c;
            float av[4] = {a1k.x, a1k.y, a1k.z, a1k.w};
            float bv[4] = {b1k.x, b1k.y, b1k.z, b1k.w};
            #pragma unroll
            for (int e = 0; e < 4; e++) {
                sKH[(w * 7 + j) * 68 + c] = av[e];
                sKW[(w * 7 + j) * 68 + c] = bv[e];
                if (++j == 7) { j = 0; c++; }
            }
        }
        if (tid < 16) {
            int ic = tid + 768;
            float4 aq = q1[ic], bq = q2[ic], ak = k1[ic], bk = k2[ic];
            int g = ic >> 4, c4 = ic & 15;
            ((float4*)(sQH + g * 68))[c4] = aq;
            ((float4*)(sQW + g * 68))[c4] = bq;
            int w = ic / 112, r4 = ic - w * 112, r = 4 * r4;
            int c = r / 7, j = r - 7 * c;
            float av[4] = {ak.x, ak.y, ak.z, ak.w};
            float bv[4] = {bk.x, bk.y, bk.z, bk.w};
            #pragma unroll
            for (int e = 0; e < 4; e++) {
                sKH[(w * 7 + j) * 68 + c] = av[e];
                sKW[(w * 7 + j) * 68 + c] = bv[e];
                if (++j == 7) { j = 0; c++; }
            }
        }
    }
    __syncthreads();

    if (tid < 343) {
        const int a0 = tid / 49;
        const int r  = tid - a0 * 49;
        const int a1 = r / 7;
        const int a2 = r - a1 * 7;

        {
            const float4* q = (const float4*)(sQH + (a0 * 7 + a1) * 68);
            const float4* k = (const float4*)(sKH + (a0 * 7 + a2) * 68);
            float s = 0.f;
            #pragma unroll
            for (int c4 = 0; c4 < 16; c4++) {
                float4 qa = q[c4], ka = k[c4];
                s = fmaf(qa.x, ka.x, s); s = fmaf(qa.y, ka.y, s);
                s = fmaf(qa.z, ka.z, s); s = fmaf(qa.w, ka.w, s);
            }
            sL[(a1 * 7 + a0) * 16 + a2] = (a1 == a2) ? NEGV : s;
        }
        {
            const float4* q = (const float4*)(sQW + (a0 * 7 + a1) * 68);
            const float4* k = (const float4*)(sKW + (a0 * 7 + a2) * 68);
            float s = 0.f;
            #pragma unroll
            for (int c4 = 0; c4 < 16; c4++) {
                float4 qa = q[c4], ka = k[c4];
                s = fmaf(qa.x, ka.x, s); s = fmaf(qa.y, ka.y, s);
                s = fmaf(qa.z, ka.z, s); s = fmaf(qa.w, ka.w, s);
            }
            sL[(a0 * 7 + a1) * 16 + 8 + a2] = s;
        }
    }
    __syncthreads();

    if (tid < GG) {
        const float* row = sL + tid * 16;
        float m = row[0];
        #pragma unroll
        for (int i = 1; i < 7; i++)  m = fmaxf(m, row[i]);
        #pragma unroll
        for (int i = 8; i < 15; i++) m = fmaxf(m, row[i]);
        float e[16], sum = 0.f;
        #pragma unroll
        for (int i = 0; i < 7; i++)  { e[i] = __expf(row[i] - m); sum += e[i]; }
        #pragma unroll
        for (int i = 8; i < 15; i++) { e[i] = __expf(row[i] - m); sum += e[i]; }
        float inv = 1.f / sum;
        float4* dst = (float4*)&g_p[((size_t)n * GG + tid) * 16];
        dst[0] = make_float4(e[0] * inv,  e[1] * inv,  e[2] * inv,  e[3] * inv);
        dst[1] = make_float4(e[4] * inv,  e[5] * inv,  e[6] * inv,  0.f);
        dst[2] = make_float4(e[8] * inv,  e[9] * inv,  e[10] * inv, e[11] * inv);
        dst[3] = make_float4(e[12] * inv, e[13] * inv, e[14] * inv, 0.f);
    }
}

// ---------------------------------------------------------------------------
// Kernel B: out[n,c,h,w] = sum_j p[pos][j]*vH[n,w,c,j] + sum_y p[pos][8+y]*vW[n,h,c,y]
// grid = (N, Cv/64), block = 64 (lane = channel in 64-chunk), 4096 blocks.
// V + p staged via cp.async (coalesced 16B, 1 wf per line, no reg round trip).
// smem 28.2KB/block -> 7-8 independent blocks/SM; barriers gate only 2 warps,
// so other blocks hide stage latency. vh cached in 49 regs; conflict-free
// stride-7 LDS; sOut aliases consumed sVH; coalesced float4 writeout.
// ---------------------------------------------------------------------------
__global__ __launch_bounds__(64, 8) void ax_attn_out(
    const float* __restrict__ vH, const float* __restrict__ vW,
    float* __restrict__ out, int Cv)
{
    extern __shared__ float smB[];
    float* sVH = smB;            // [g][(c,j)] 7*64*7 = 3136 (aliased as sOut)
    float* sVW = smB + 3136;     // 3136
    float* sP  = smB + 6272;     // 49*16 = 784

    const int n   = blockIdx.x;
    const int c0  = blockIdx.y * 64;
    const int tid = threadIdx.x;

    const uint32_t svh = smem_u32(sVH);
    const uint32_t svw = smem_u32(sVW);
    const uint32_t sp  = smem_u32(sP);

    // ---- async stage: vH + vW chunks (784 float4 each) + p (196 float4) ----
    #pragma unroll
    for (int u = 0; u < 12; u++) {
        int i4 = tid + u * 64;                  // 0..767
        int g = i4 / 112, r = i4 - g * 112;
        const float4* gh = (const float4*)(vH + ((size_t)(n * 7 + g) * Cv + c0) * 7);
        const float4* gw = (const float4*)(vW + ((size_t)(n * 7 + g) * Cv + c0) * 7);
        CP_ASYNC16(svh + i4 * 16, gh + r);
        CP_ASYNC16(svw + i4 * 16, gw + r);
    }
    if (tid < 16) {                             // tail i4 = 768..783 (g=6)
        int i4 = 768 + tid, r = i4 - 672;
        const float4* gh = (const float4*)(vH + ((size_t)(n * 7 + 6) * Cv + c0) * 7);
        const float4* gw = (const float4*)(vW + ((size_t)(n * 7 + 6) * Cv + c0) * 7);
        CP_ASYNC16(svh + i4 * 16, gh + r);
        CP_ASYNC16(svw + i4 * 16, gw + r);
    }
    {
        const float4* pg = (const float4*)&g_p[(size_t)n * GG * 16];
        #pragma unroll
        for (int u = 0; u < 3; u++) {
            int i = tid + u * 64;
            CP_ASYNC16(sp + i * 16, pg + i);
        }
        if (tid < 4) CP_ASYNC16(sp + (192 + tid) * 16, pg + 192 + tid);
    }
    CP_COMMIT();
    CP_WAIT0();
    __syncthreads();

    // ---- cache this thread's vH (stride 7, coprime 32 -> conflict-free) ----
    float vh[49];
    #pragma unroll
    for (int w = 0; w < 7; w++)
        #pragma unroll
        for (int j = 0; j < 7; j++)
            vh[w * 7 + j] = sVH[w * 448 + tid * 7 + j];
    __syncthreads();   // all vH consumed -> safe to alias as sOut

    float* sOut = sVH;
    #pragma unroll
    for (int h = 0; h < 7; h++) {
        float vw0 = sVW[h * 448 + tid * 7 + 0];
        float vw1 = sVW[h * 448 + tid * 7 + 1];
        float vw2 = sVW[h * 448 + tid * 7 + 2];
        float vw3 = sVW[h * 448 + tid * 7 + 3];
        float vw4 = sVW[h * 448 + tid * 7 + 4];
        float vw5 = sVW[h * 448 + tid * 7 + 5];
        float vw6 = sVW[h * 448 + tid * 7 + 6];
        #pragma unroll
        for (int w = 0; w < 7; w++) {
            const float4* p4 = (const float4*)(sP + (h * 7 + w) * 16);
            float4 a = p4[0], b = p4[1], c4 = p4[2], d4 = p4[3];
            float s = a.x * vh[w * 7 + 0];
            s = fmaf(a.y, vh[w * 7 + 1], s);
            s = fmaf(a.z, vh[w * 7 + 2], s);
            s = fmaf(a.w, vh[w * 7 + 3], s);
            s = fmaf(b.x, vh[w * 7 + 4], s);
            s = fmaf(b.y, vh[w * 7 + 5], s);
            s = fmaf(b.z, vh[w * 7 + 6], s);
            s = fmaf(c4.x, vw0, s);
            s = fmaf(c4.y, vw1, s);
            s = fmaf(c4.z, vw2, s);
            s = fmaf(c4.w, vw3, s);
            s = fmaf(d4.x, vw4, s);
            s = fmaf(d4.y, vw5, s);
            s = fmaf(d4.z, vw6, s);
            sOut[tid * 49 + h * 7 + w] = s;   // stride 49 (coprime 32)
        }
    }
    __syncthreads();

    // coalesced float4 writeout: sOut[c_local*49 + pos] == out[n, c0+c_local, pos]
    float* dst = out + ((size_t)n * Cv + c0) * GG;
    #pragma unroll
    for (int u = 0; u < 12; u++)
        ((float4*)dst)[tid + u * 64] = ((const float4*)sOut)[tid + u * 64];
    if (tid < 16)
        ((float4*)dst)[768 + tid] = ((const float4*)sOut)[768 + tid];
}

// ---------------------------------------------------------------------------
extern "C" void kernel_launch(void* const* d_in, const int* in_sizes, int n_in,
                              void* d_out, int out_size)
{
    const float* qH = (const float*)d_in[0];
    const float* kH = (const float*)d_in[1];
    const float* vH = (const float*)d_in[2];
    const float* qW = (const float*)d_in[3];
    const float* kW = (const float*)d_in[4];
    const float* vW = (const float*)d_in[5];

    const int B  = in_sizes[0] / (7 * CQ);    // 3584
    const int N  = B / 7;                     // 512
    const int Cv = in_sizes[2] / (B * 7);     // 512

    const size_t smemA = (size_t)14112 * sizeof(float);  // 56448
    const size_t smemB = (size_t)7056  * sizeof(float);  // 28224
    cudaFuncSetAttribute(ax_attn_logits, cudaFuncAttributeMaxDynamicSharedMemorySize, (int)smemA);
    cudaFuncSetAttribute(ax_attn_out,    cudaFuncAttributeMaxDynamicSharedMemorySize, (int)smemB);

    ax_attn_logits<<<N, 384, smemA>>>(qH, kH, qW, kW);
    ax_attn_out<<<dim3(N, Cv / 64), 64, smemB>>>(vH, vW, (float*)d_out, Cv);
}

// round 11
// speedup vs baseline: 1.1496x; 1.1496x over previous
#include <cuda_runtime.h>

#define GG    49
#define CQ    64
#define NEGV  (-1e20f)

// Softmax probabilities scratch: [n][49][16]; pH at slots 0..6 (7=0), pW at 8..14 (15=0).
__device__ float g_p[512 * GG * 16];

// ---------------------------------------------------------------------------
// Kernel A: logits (H diag-masked + W) + softmax over 14, per n.
// grid = N, block = 256, __launch_bounds__(256,4) caps regs at 64 so the
// register file allows the smem-limited 4 blocks/SM -> 512 blocks = ONE wave.
// Staging in two bounded batches (<=8 LDG.128 live). k scattered to
// transposed [w*7+j][c] rows; dots are 32 x LDS.128 + 64 FMA (2 accums).
// ---------------------------------------------------------------------------
__global__ __launch_bounds__(256, 4) void ax_attn_logits(
    const float* __restrict__ qH, const float* __restrict__ kH,
    const float* __restrict__ qW, const float* __restrict__ kW)
{
    extern __shared__ float smA[];
    float* sQH = smA;              // 49 * 68
    float* sKH = smA + 3332;       // transposed [w*7+j][c], 49 * 68
    float* sQW = smA + 6664;
    float* sKW = smA + 9996;
    float* sL  = smA + 13328;      // 49 * 16

    const int n   = blockIdx.x;
    const int tid = threadIdx.x;

    const float4* q1 = (const float4*)(qH + (size_t)n * 3136);
    const float4* q2 = (const float4*)(qW + (size_t)n * 3136);
    const float4* k1 = (const float4*)(kH + (size_t)n * 3136);
    const float4* k2 = (const float4*)(kW + (size_t)n * 3136);

    // k scatter helper (macro-style to avoid function reg overhead)
    #define SCATTER_K(i4, vk1, vk2)                                   \
    {                                                                 \
        int w = (i4) / 112, r4 = (i4) - w * 112, r = 4 * r4;          \
        int c = r / 7, j = r - 7 * c;                                 \
        float av[4] = {(vk1).x, (vk1).y, (vk1).z, (vk1).w};           \
        float bv[4] = {(vk2).x, (vk2).y, (vk2).z, (vk2).w};           \
        _Pragma("unroll")                                             \
        for (int e = 0; e < 4; e++) {                                 \
            sKH[(w * 7 + j) * 68 + c] = av[e];                        \
            sKW[(w * 7 + j) * 68 + c] = bv[e];                        \
            if (++j == 7) { j = 0; c++; }                             \
        }                                                             \
    }
    #define STORE_Q(i4, vq1, vq2)                                     \
    {                                                                 \
        int g = (i4) >> 4, c4 = (i4) & 15;                            \
        ((float4*)(sQH + g * 68))[c4] = (vq1);                        \
        ((float4*)(sQW + g * 68))[c4] = (vq2);                        \
    }

    // batch 1: i4 = tid, tid+256  (8 LDG.128 in flight)
    {
        int ia = tid, ib = tid + 256;
        float4 aq1 = q1[ia], aq2 = q2[ia], ak1 = k1[ia], ak2 = k2[ia];
        float4 bq1 = q1[ib], bq2 = q2[ib], bk1 = k1[ib], bk2 = k2[ib];
        STORE_Q(ia, aq1, aq2); SCATTER_K(ia, ak1, ak2);
        STORE_Q(ib, bq1, bq2); SCATTER_K(ib, bk1, bk2);
    }
    // batch 2: i4 = tid+512, tail 768+tid (tid<16)
    {
        int ic = tid + 512;
        float4 cq1 = q1[ic], cq2 = q2[ic], ck1 = k1[ic], ck2 = k2[ic];
        if (tid < 16) {
            int id = tid + 768;
            float4 dq1 = q1[id], dq2 = q2[id], dk1 = k1[id], dk2 = k2[id];
            STORE_Q(ic, cq1, cq2); SCATTER_K(ic, ck1, ck2);
            STORE_Q(id, dq1, dq2); SCATTER_K(id, dk1, dk2);
        } else {
            STORE_Q(ic, cq1, cq2); SCATTER_K(ic, ck1, ck2);
        }
    }
    #undef SCATTER_K
    #undef STORE_Q
    __syncthreads();

    // 343 dot-pairs over 256 threads
    #pragma unroll
    for (int u = 0; u < 2; u++) {
        int idx = tid + u * 256;
        if (idx < 343) {
            const int a0 = idx / 49;
            const int r  = idx - a0 * 49;
            const int a1 = r / 7;
            const int a2 = r - a1 * 7;

            // H: logits[n, h=a1, w=a0, a2] = dot(qH[n,a0,a1,:], kH[n,a0,:,a2])
            {
                const float4* q = (const float4*)(sQH + (a0 * 7 + a1) * 68);
                const float4* k = (const float4*)(sKH + (a0 * 7 + a2) * 68);
                float s0 = 0.f, s1 = 0.f;
                #pragma unroll
                for (int c4 = 0; c4 < 16; c4 += 2) {
                    float4 qa = q[c4],     ka = k[c4];
                    float4 qb = q[c4 + 1], kb = k[c4 + 1];
                    s0 = fmaf(qa.x, ka.x, s0); s0 = fmaf(qa.y, ka.y, s0);
                    s0 = fmaf(qa.z, ka.z, s0); s0 = fmaf(qa.w, ka.w, s0);
                    s1 = fmaf(qb.x, kb.x, s1); s1 = fmaf(qb.y, kb.y, s1);
                    s1 = fmaf(qb.z, kb.z, s1); s1 = fmaf(qb.w, kb.w, s1);
                }
                sL[(a1 * 7 + a0) * 16 + a2] = (a1 == a2) ? NEGV : (s0 + s1);
            }
            // W: logits[n, h=a0, w=a1, 8+a2] = dot(qW[n,a0,a1,:], kW[n,a0,:,a2])
            {
                const float4* q = (const float4*)(sQW + (a0 * 7 + a1) * 68);
                const float4* k = (const float4*)(sKW + (a0 * 7 + a2) * 68);
                float s0 = 0.f, s1 = 0.f;
                #pragma unroll
                for (int c4 = 0; c4 < 16; c4 += 2) {
                    float4 qa = q[c4],     ka = k[c4];
                    float4 qb = q[c4 + 1], kb = k[c4 + 1];
                    s0 = fmaf(qa.x, ka.x, s0); s0 = fmaf(qa.y, ka.y, s0);
                    s0 = fmaf(qa.z, ka.z, s0); s0 = fmaf(qa.w, ka.w, s0);
                    s1 = fmaf(qb.x, kb.x, s1); s1 = fmaf(qb.y, kb.y, s1);
                    s1 = fmaf(qb.z, kb.z, s1); s1 = fmaf(qb.w, kb.w, s1);
                }
                sL[(a0 * 7 + a1) * 16 + 8 + a2] = s0 + s1;
            }
        }
    }
    __syncthreads();

    if (tid < GG) {
        const float* row = sL + tid * 16;
        float m = row[0];
        #pragma unroll
        for (int i = 1; i < 7; i++)  m = fmaxf(m, row[i]);
        #pragma unroll
        for (int i = 8; i < 15; i++) m = fmaxf(m, row[i]);
        float e[16], sum = 0.f;
        #pragma unroll
        for (int i = 0; i < 7; i++)  { e[i] = __expf(row[i] - m); sum += e[i]; }
        #pragma unroll
        for (int i = 8; i < 15; i++) { e[i] = __expf(row[i] - m); sum += e[i]; }
        float inv = 1.f / sum;
        float4* dst = (float4*)&g_p[((size_t)n * GG + tid) * 16];
        dst[0] = make_float4(e[0] * inv,  e[1] * inv,  e[2] * inv,  e[3] * inv);
        dst[1] = make_float4(e[4] * inv,  e[5] * inv,  e[6] * inv,  0.f);
        dst[2] = make_float4(e[8] * inv,  e[9] * inv,  e[10] * inv, e[11] * inv);
        dst[3] = make_float4(e[12] * inv, e[13] * inv, e[14] * inv, 0.f);
    }
}

// ---------------------------------------------------------------------------
// Kernel B (R8 proven best, byte-identical): direct GMEM->reg V loads,
// p in smem, sOut transpose staging for coalesced writeout.
// grid = (N, Cv/128), block = 128, smem 28.2KB -> 5 blocks/SM.
// ---------------------------------------------------------------------------
__global__ __launch_bounds__(128, 5) void ax_attn_out(
    const float* __restrict__ vH, const float* __restrict__ vW,
    float* __restrict__ out, int Cv)
{
    __shared__ float sOut[7 * 7 * 128];   // 6272
    __shared__ float sP[GG * 16];         // 784

    const int n   = blockIdx.x;
    const int c0  = blockIdx.y * 128;
    const int tid = threadIdx.x;
    const int c   = c0 + tid;
    const int ws  = Cv * 7;               // per-g stride in floats

    const float* bH = vH + (size_t)n * Cv * 49 + (size_t)c * 7;
    const float* bW = vW + (size_t)n * Cv * 49 + (size_t)c * 7;

    // direct GMEM->reg vH loads: 49 independent LDGs, issued up front
    float vh[49];
    #pragma unroll
    for (int w = 0; w < 7; w++)
        #pragma unroll
        for (int j = 0; j < 7; j++)
            vh[w * 7 + j] = bH[w * ws + j];

    // stage p to smem (overlaps with vh loads in flight)
    {
        const float4* pg = (const float4*)&g_p[(size_t)n * GG * 16];
        float4 p0 = pg[tid];
        float4 p1; bool hp1 = (tid < 68);
        if (hp1) p1 = pg[tid + 128];
        ((float4*)sP)[tid] = p0;
        if (hp1) ((float4*)sP)[tid + 128] = p1;
    }
    __syncthreads();

    #pragma unroll
    for (int h = 0; h < 7; h++) {
        const float* bWh = bW + h * ws;
        float vw0 = bWh[0], vw1 = bWh[1], vw2 = bWh[2], vw3 = bWh[3];
        float vw4 = bWh[4], vw5 = bWh[5], vw6 = bWh[6];
        #pragma unroll
        for (int w = 0; w < 7; w++) {
            const float4* p4 = (const float4*)(sP + (h * 7 + w) * 16);
            float4 a = p4[0], b = p4[1], c4 = p4[2], d4 = p4[3];
            float s = a.x * vh[w * 7 + 0];
            s = fmaf(a.y, vh[w * 7 + 1], s);
            s = fmaf(a.z, vh[w * 7 + 2], s);
            s = fmaf(a.w, vh[w * 7 + 3], s);
            s = fmaf(b.x, vh[w * 7 + 4], s);
            s = fmaf(b.y, vh[w * 7 + 5], s);
            s = fmaf(b.z, vh[w * 7 + 6], s);
            s = fmaf(c4.x, vw0, s);
            s = fmaf(c4.y, vw1, s);
            s = fmaf(c4.z, vw2, s);
            s = fmaf(c4.w, vw3, s);
            s = fmaf(d4.x, vw4, s);
            s = fmaf(d4.y, vw5, s);
            s = fmaf(d4.z, vw6, s);
            sOut[tid * 49 + h * 7 + w] = s;   // stride 49 (coprime 32) -> conflict-free
        }
    }
    __syncthreads();

    // coalesced float4 write-out: sOut[c_local*49 + pos] == out[n, c0+c_local, pos]
    float* dst = out + ((size_t)n * Cv + c0) * GG;
    #pragma unroll
    for (int u = 0; u < 12; u++)
        ((float4*)dst)[tid + u * 128] = ((const float4*)sOut)[tid + u * 128];
    if (tid < 32)
        ((float4*)dst)[1536 + tid] = ((const float4*)sOut)[1536 + tid];
}

// ---------------------------------------------------------------------------
extern "C" void kernel_launch(void* const* d_in, const int* in_sizes, int n_in,
                              void* d_out, int out_size)
{
    const float* qH = (const float*)d_in[0];
    const float* kH = (const float*)d_in[1];
    const float* vH = (const float*)d_in[2];
    const float* qW = (const float*)d_in[3];
    const float* kW = (const float*)d_in[4];
    const float* vW = (const float*)d_in[5];

    const int B  = in_sizes[0] / (7 * CQ);    // 3584
    const int N  = B / 7;                     // 512
    const int Cv = in_sizes[2] / (B * 7);     // 512

    const size_t smemA = (size_t)14112 * sizeof(float);  // 56448
    cudaFuncSetAttribute(ax_attn_logits, cudaFuncAttributeMaxDynamicSharedMemorySize, (int)smemA);

    ax_attn_logits<<<N, 256, smemA>>>(qH, kH, qW, kW);
    ax_attn_out<<<dim3(N, Cv / 128), 128>>>(vH, vW, (float*)d_out, Cv);
}